// round 10
// baseline (speedup 1.0000x reference)
#include <cuda_runtime.h>
#include <cuda_fp16.h>
#include <cstdint>

#define NB   16
#define CIN  256
#define COUT 256
#define KS   5
#define SPK  128
#define TLEN 8192
#define TP   8196    // padded t rows (t=-2..8193)

#define OTI  64      // o tile per block
#define TTI  256     // t tile per block
#define ICH  32      // i chunk
#define XR   40      // padded row pitch (80B -> 16B-aligned quarters)
#define XT   260     // xs rows (t range: tile + 4 pad)
#define NCH  8       // CIN / ICH

#define XS_ST (XT * XR)          // 10400 elems per stage
#define WS_ST (KS * OTI * XR)    // 12800 elems per stage
#define SMEM_BYTES ((2 * XS_ST + 2 * WS_ST) * 2)   // 92800

// scratch (no cudaMalloc allowed)
__device__ float g_s[NB * CIN];
__device__ float g_demod[NB * COUT];
__device__ float g_wsqT[CIN * COUT];                         // [i][o]
__device__ __half g_wm[(size_t)NB * KS * COUT * CIN];        // [b][k][o][i]
__device__ __half g_xT[(size_t)NB * TP * CIN];               // [b][t+2][i]

// ---------------------------------------------------------------------------
__global__ void style_kernel(const float* __restrict__ c_trg,
                             const float* __restrict__ style_w,
                             const float* __restrict__ style_b) {
    int b = blockIdx.x;
    int i = threadIdx.x;
    const float* c = c_trg + b * SPK;
    const float* w = style_w + i * SPK;
    float acc = 0.f;
#pragma unroll 8
    for (int j = 0; j < SPK; ++j) acc += c[j] * w[j];
    g_s[b * CIN + i] = acc + style_b[i];
}

__global__ void wsq_kernel(const float* __restrict__ weight) {
    int i = blockIdx.x;
    int o = threadIdx.x;
    const float* wp = weight + ((size_t)o * CIN + i) * KS;
    float acc = 0.f;
#pragma unroll
    for (int k = 0; k < KS; ++k) acc += wp[k] * wp[k];
    g_wsqT[i * COUT + o] = acc;
}

__global__ void demod_kernel() {
    int b = blockIdx.x;
    int o = threadIdx.x;
    const float* sp = g_s + b * CIN;
    float acc = 0.f;
#pragma unroll 4
    for (int i = 0; i < CIN; ++i) {
        float s = sp[i];
        acc += s * s * g_wsqT[i * COUT + o];
    }
    g_demod[b * COUT + o] = rsqrtf(acc + 1e-8f);
}

// g_wm[b][k][o][i] = fp16( weight[o,i,k]*s[b,i]*demod[b,o] )
__global__ void wm_kernel(const float* __restrict__ weight) {
    int idx = blockIdx.x * blockDim.x + threadIdx.x;   // NB*KS*COUT*CIN
    int i = idx & (CIN - 1);
    int o = (idx >> 8) & (COUT - 1);
    int kb = idx >> 16;
    int k = kb % KS;
    int b = kb / KS;
    float wv = weight[((size_t)o * CIN + i) * KS + k]
             * g_s[b * CIN + i] * g_demod[b * COUT + o];
    g_wm[idx] = __float2half_rn(wv);
}

// x transpose + fp16: g_xT[b][t+2][i] = fp16(x[b][i][t]), interior rows
__global__ void xt_kernel(const float* __restrict__ x) {
    __shared__ __half ts[32][258];
    int b  = blockIdx.y;
    int t0 = blockIdx.x * 32;
    int tt = threadIdx.x & 31;
    int iw = threadIdx.x >> 5;         // 0..7
    const float* xb = x + (size_t)b * CIN * TLEN;
#pragma unroll
    for (int it = 0; it < 32; ++it) {
        int i = it * 8 + iw;
        ts[tt][i] = __float2half_rn(xb[(size_t)i * TLEN + t0 + tt]);
    }
    __syncthreads();
    __half* dst = g_xT + ((size_t)b * TP + t0 + 2) * CIN;
#pragma unroll
    for (int j = 0; j < 32; ++j)
        dst[(size_t)j * CIN + threadIdx.x] = ts[j][threadIdx.x];
}

// reflect-pad edge rows of g_xT
__global__ void xedge_kernel(const float* __restrict__ x) {
    int v = blockIdx.x * 256 + threadIdx.x;   // < NB*4*256
    int i = v & 255;
    int e = (v >> 8) & 3;
    int b = v >> 10;
    int tp = (e < 2) ? e : (TP - 4 + e);      // rows 0,1, 8194,8195
    int t  = tp - 2;
    t = (t < 0) ? -t : ((t >= TLEN) ? (2 * TLEN - 2 - t) : t);
    g_xT[((size_t)b * TP + tp) * CIN + i] =
        __float2half_rn(x[((size_t)b * CIN + i) * TLEN + t]);
}

// ---------------------------------------------------------------------------
__device__ __forceinline__ void mma16816(float* d, const unsigned* a,
                                         unsigned b0, unsigned b1) {
    asm volatile(
        "mma.sync.aligned.m16n8k16.row.col.f32.f16.f16.f32 "
        "{%0,%1,%2,%3}, {%4,%5,%6,%7}, {%8,%9}, {%0,%1,%2,%3};"
        : "+f"(d[0]), "+f"(d[1]), "+f"(d[2]), "+f"(d[3])
        : "r"(a[0]), "r"(a[1]), "r"(a[2]), "r"(a[3]), "r"(b0), "r"(b1));
}
__device__ __forceinline__ unsigned lds32(const __half* p) {
    return *(const unsigned*)p;
}
__device__ __forceinline__ uint32_t smem_u32(const void* p) {
    uint32_t a;
    asm("{ .reg .u64 t; cvta.to.shared.u64 t, %1; cvt.u32.u64 %0, t; }"
        : "=r"(a) : "l"(p));
    return a;
}
__device__ __forceinline__ void cp16(uint32_t dst, const void* src) {
    asm volatile("cp.async.cg.shared.global [%0], [%1], 16;"
                 :: "r"(dst), "l"(src));
}
#define CP_COMMIT() asm volatile("cp.async.commit_group;" ::: "memory")
#define CP_WAIT0()  asm volatile("cp.async.wait_group 0;" ::: "memory")

// ---------------------------------------------------------------------------
// Main conv: out[b,o,t] = leaky( sum_{i,k} Wm[b,o,i,k] * x_reflpad[b,i,t+k] )
// fp16 mma.sync, all operand fills via cp.async, 2 CTAs/SM.
__global__ __launch_bounds__(256, 2)
void conv_kernel(const float* __restrict__ x, float* __restrict__ out) {
    extern __shared__ __align__(16) __half sm[];
    __half* xs = sm;                        // [2][XS_ST]
    __half* ws = sm + 2 * XS_ST;            // [2][WS_ST]
    const uint32_t xs_a = smem_u32(xs);
    const uint32_t ws_a = smem_u32(ws);

    const int b  = blockIdx.z;
    const int ob = blockIdx.y * OTI;
    const int tb = blockIdx.x * TTI;
    const int tid = threadIdx.x;
    const int wid = tid >> 5;
    const int lane = tid & 31;
    const int wo = wid & 1;           // o warp (2): 32 o each
    const int wt = wid >> 1;          // t warp (4): 64 t each
    const int lq = lane >> 2;
    const int lr = lane & 3;

    float acc[2][8][4];
#pragma unroll
    for (int mt = 0; mt < 2; ++mt)
#pragma unroll
        for (int nt = 0; nt < 8; ++nt)
#pragma unroll
            for (int e = 0; e < 4; ++e) acc[mt][nt][e] = 0.f;

    const __half* wmb = g_wm + (size_t)b * KS * COUT * CIN;
    const __half* xtb = g_xT + ((size_t)b * TP + tb) * CIN;   // row u = t offset

    // ---- prefetch Ws: 320 rows x 4 aligned 16B chunks ----
    auto prefetch_w = [&](int ic, int st) {
#pragma unroll
        for (int m = 0; m < 5; ++m) {
            int v = tid + 256 * m;                  // < 1280
            int row = v >> 2;                        // k*OTI + o
            int c4  = v & 3;
            int k = row >> 6;
            int o = row & 63;
            const __half* src =
                wmb + ((size_t)(k * COUT + ob + o) * CIN + ic) + c4 * 8;
            uint32_t dst = ws_a + (uint32_t)(st * WS_ST + row * XR) * 2 + c4 * 16;
            cp16(dst, src);
        }
    };
    // ---- prefetch Xs: 260 rows x 4 aligned 16B chunks ----
    auto prefetch_x = [&](int ic, int st) {
#pragma unroll
        for (int m = 0; m < 5; ++m) {
            int v = tid + 256 * m;
            if (v < XT * 4) {
                int row = v >> 2;                    // u = 0..259
                int c4  = v & 3;
                const __half* src = xtb + (size_t)row * CIN + ic + c4 * 8;
                uint32_t dst = xs_a + (uint32_t)(st * XS_ST + row * XR) * 2 + c4 * 16;
                cp16(dst, src);
            }
        }
    };

    // ---- prologue: fill stage 0 ----
    prefetch_w(0, 0);
    prefetch_x(0, 0);
    CP_COMMIT();
    CP_WAIT0();
    __syncthreads();

    for (int c = 0; c < NCH; ++c) {
        const int st = c & 1;
        const int nst = st ^ 1;
        if (c + 1 < NCH) {
            prefetch_w((c + 1) * ICH, nst);
            prefetch_x((c + 1) * ICH, nst);
            CP_COMMIT();
        }

        // ---- MMA over stage st ----
        const __half* wsp = ws + st * WS_ST;
        const __half* xsp = xs + st * XS_ST;

        for (int tap = 0; tap < KS; ++tap) {
#pragma unroll
            for (int k16 = 0; k16 < ICH; k16 += 16) {
                unsigned ah[2][4];
#pragma unroll
                for (int mt = 0; mt < 2; ++mt) {
                    int row = tap * OTI + wo * 32 + mt * 16 + lq;
                    int col = k16 + lr * 2;
                    const __half* ph = wsp + row * XR + col;
                    ah[mt][0] = lds32(ph);
                    ah[mt][1] = lds32(ph + 8 * XR);
                    ah[mt][2] = lds32(ph + 8);
                    ah[mt][3] = lds32(ph + 8 * XR + 8);
                }
#pragma unroll
                for (int nt = 0; nt < 8; ++nt) {
                    int trow = wt * 64 + nt * 8 + lq + tap;
                    int col  = k16 + lr * 2;
                    const __half* ph = xsp + trow * XR + col;
                    unsigned bh0 = lds32(ph), bh1 = lds32(ph + 8);
#pragma unroll
                    for (int mt = 0; mt < 2; ++mt)
                        mma16816(acc[mt][nt], ah[mt], bh0, bh1);
                }
            }
        }

        if (c + 1 < NCH) CP_WAIT0();
        __syncthreads();
    }

    // ---- epilogue: leaky relu + store ----
#pragma unroll
    for (int mt = 0; mt < 2; ++mt) {
#pragma unroll
        for (int nt = 0; nt < 8; ++nt) {
            int o0 = ob + wo * 32 + mt * 16 + lq;
            int t0 = tb + wt * 64 + nt * 8 + lr * 2;
            float z0 = acc[mt][nt][0], z1 = acc[mt][nt][1];
            float z2 = acc[mt][nt][2], z3 = acc[mt][nt][3];
            z0 = (z0 > 0.f) ? z0 : 0.2f * z0;
            z1 = (z1 > 0.f) ? z1 : 0.2f * z1;
            z2 = (z2 > 0.f) ? z2 : 0.2f * z2;
            z3 = (z3 > 0.f) ? z3 : 0.2f * z3;
            float* p0 = out + ((size_t)b * COUT + o0) * TLEN + t0;
            *(float2*)p0 = make_float2(z0, z1);
            *(float2*)(p0 + 8 * TLEN) = make_float2(z2, z3);
        }
    }
}

// ---------------------------------------------------------------------------
extern "C" void kernel_launch(void* const* d_in, const int* in_sizes, int n_in,
                              void* d_out, int out_size) {
    const float* x       = (const float*)d_in[0];   // [16,256,8192]
    const float* c_trg   = (const float*)d_in[1];   // [16,128]
    const float* style_w = (const float*)d_in[2];   // [256,128]
    const float* style_b = (const float*)d_in[3];   // [256]
    const float* weight  = (const float*)d_in[4];   // [1,256,256,5]
    float* out = (float*)d_out;

    style_kernel<<<NB, CIN>>>(c_trg, style_w, style_b);
    wsq_kernel<<<CIN, COUT>>>(weight);
    {
        dim3 g(TLEN / 32, NB);
        xt_kernel<<<g, 256>>>(x);
    }
    xedge_kernel<<<NB * 4, 256>>>(x);
    demod_kernel<<<NB, COUT>>>();
    wm_kernel<<<(NB * KS * CIN * COUT) / 256, 256>>>(weight);

    static bool attr_done = false;
    if (!attr_done) {
        cudaFuncSetAttribute(conv_kernel,
                             cudaFuncAttributeMaxDynamicSharedMemorySize,
                             SMEM_BYTES);
        attr_done = true;
    }
    dim3 grid(TLEN / TTI, COUT / OTI, NB);        // (32, 4, 16)
    conv_kernel<<<grid, 256, SMEM_BYTES>>>(x, out);

    size_t conv_elems = (size_t)NB * COUT * TLEN;
    if ((size_t)out_size > conv_elems) {
        cudaMemcpyAsync(out + conv_elems, c_trg,
                        (out_size - conv_elems) * sizeof(float),
                        cudaMemcpyDeviceToDevice);
    }
}

// round 11
// speedup vs baseline: 1.0648x; 1.0648x over previous
#include <cuda_runtime.h>
#include <cuda_fp16.h>
#include <cstdint>

#define NB   16
#define CIN  256
#define COUT 256
#define KS   5
#define SPK  128
#define TLEN 8192

#define OTI  128     // o tile per block (4 o-warps)
#define TTI  256     // t tile per block (4 t-warps)
#define ICH  32      // i chunk
#define XR   40      // padded row pitch (80B -> 16B-aligned quarters)
#define XT   260     // xs rows (t range: tile + 4 pad)
#define NCH  8       // CIN / ICH
#define NTH  512

#define XS_ST (XT * XR)              // 10400 elems per stage
#define WS_ST (KS * OTI * XR)        // 25600 elems per stage
#define SMEM_BYTES ((2 * XS_ST + 2 * WS_ST) * 2)   // 144000

// scratch (no cudaMalloc allowed)
__device__ float g_s[NB * CIN];
__device__ float g_demod[NB * COUT];
__device__ __half g_wm[(size_t)NB * KS * COUT * CIN];        // [b][k][o][i]

// ---------------------------------------------------------------------------
// Fused: style GEMV + demod (wsq recomputed on the fly). grid=NB, block=256.
__global__ void prep_kernel(const float* __restrict__ c_trg,
                            const float* __restrict__ style_w,
                            const float* __restrict__ style_b,
                            const float* __restrict__ weight) {
    __shared__ float ss[CIN];
    int b = blockIdx.x;
    int tid = threadIdx.x;
    // style: s[b,i]
    {
        const float* c = c_trg + b * SPK;
        const float* w = style_w + tid * SPK;
        float acc = 0.f;
#pragma unroll 8
        for (int j = 0; j < SPK; ++j) acc += c[j] * w[j];
        acc += style_b[tid];
        ss[tid] = acc;
        g_s[b * CIN + tid] = acc;
    }
    __syncthreads();
    // demod: o = tid
    {
        int o = tid;
        const float* wp = weight + (size_t)o * CIN * KS;
        float acc = 0.f;
#pragma unroll 4
        for (int i = 0; i < CIN; ++i) {
            float wsq = 0.f;
#pragma unroll
            for (int k = 0; k < KS; ++k) {
                float w = wp[i * KS + k];
                wsq += w * w;
            }
            float s = ss[i];
            acc += s * s * wsq;
        }
        g_demod[b * COUT + o] = rsqrtf(acc + 1e-8f);
    }
}

// g_wm[b][k][o][i] = fp16( weight[o,i,k]*s[b,i]*demod[b,o] )
__global__ void wm_kernel(const float* __restrict__ weight) {
    int idx = blockIdx.x * blockDim.x + threadIdx.x;   // NB*KS*COUT*CIN
    int i = idx & (CIN - 1);
    int o = (idx >> 8) & (COUT - 1);
    int kb = idx >> 16;
    int k = kb % KS;
    int b = kb / KS;
    float wv = weight[((size_t)o * CIN + i) * KS + k]
             * g_s[b * CIN + i] * g_demod[b * COUT + o];
    g_wm[idx] = __float2half_rn(wv);
}

// ---------------------------------------------------------------------------
__device__ __forceinline__ void mma16816(float* d, const unsigned* a,
                                         unsigned b0, unsigned b1) {
    asm volatile(
        "mma.sync.aligned.m16n8k16.row.col.f32.f16.f16.f32 "
        "{%0,%1,%2,%3}, {%4,%5,%6,%7}, {%8,%9}, {%0,%1,%2,%3};"
        : "+f"(d[0]), "+f"(d[1]), "+f"(d[2]), "+f"(d[3])
        : "r"(a[0]), "r"(a[1]), "r"(a[2]), "r"(a[3]), "r"(b0), "r"(b1));
}
__device__ __forceinline__ unsigned lds32(const __half* p) {
    return *(const unsigned*)p;
}
__device__ __forceinline__ uint32_t smem_u32(const void* p) {
    uint32_t a;
    asm("{ .reg .u64 t; cvta.to.shared.u64 t, %1; cvt.u32.u64 %0, t; }"
        : "=r"(a) : "l"(p));
    return a;
}
__device__ __forceinline__ void cp16(uint32_t dst, const void* src) {
    asm volatile("cp.async.cg.shared.global [%0], [%1], 16;"
                 :: "r"(dst), "l"(src));
}
#define CP_COMMIT() asm volatile("cp.async.commit_group;" ::: "memory")
#define CP_WAIT0()  asm volatile("cp.async.wait_group 0;" ::: "memory")

__device__ __forceinline__ float ldg_f32(const float* p) {
    float v;
    asm volatile("ld.global.nc.f32 %0, [%1];" : "=f"(v) : "l"(p));
    return v;
}

// ---------------------------------------------------------------------------
// Main conv: out[b,o,t] = leaky( sum_{i,k} Wm[b,o,i,k] * x_reflpad[b,i,t+k] )
// fp16 mma.sync, 512 threads = 128o x 256t per CTA, double-buffered smem.
__global__ __launch_bounds__(NTH, 1)
void conv_kernel(const float* __restrict__ x, float* __restrict__ out) {
    extern __shared__ __align__(16) __half sm[];
    __half* xs = sm;                        // [2][XS_ST]
    __half* ws = sm + 2 * XS_ST;            // [2][WS_ST]
    const uint32_t ws_a = smem_u32(ws);

    const int b  = blockIdx.z;
    const int ob = blockIdx.y * OTI;
    const int tb = blockIdx.x * TTI;
    const int tid = threadIdx.x;
    const int wid = tid >> 5;
    const int lane = tid & 31;
    const int wo = wid & 3;           // o warp (4): 32 o each
    const int wt = wid >> 2;          // t warp (4): 64 t each
    const int lq = lane >> 2;
    const int lr = lane & 3;

    float acc[2][8][4];
#pragma unroll
    for (int mt = 0; mt < 2; ++mt)
#pragma unroll
        for (int nt = 0; nt < 8; ++nt)
#pragma unroll
            for (int e = 0; e < 4; ++e) acc[mt][nt][e] = 0.f;

    const float* xb = x + (size_t)b * CIN * TLEN;
    const __half* wmb = g_wm + (size_t)b * KS * COUT * CIN;

    float xr[17];

    // ---- prefetch Ws: 640 rows x 4 aligned 16B chunks = 2560 cp16 ----
    auto prefetch_w = [&](int ic, int st) {
#pragma unroll
        for (int m = 0; m < 5; ++m) {
            int v = tid + NTH * m;                  // < 2560
            int row = v >> 2;                        // k*OTI + o  (0..639)
            int c4  = v & 3;
            int k = row >> 7;
            int o = row & 127;
            const __half* src =
                wmb + ((size_t)(k * COUT + ob + o) * CIN + ic) + c4 * 8;
            uint32_t dst = ws_a + (uint32_t)(st * WS_ST + row * XR) * 2 + c4 * 16;
            cp16(dst, src);
        }
        CP_COMMIT();
    };
    // ---- issue x LDGs for chunk into regs (latency hidden under MMAs) ----
    auto load_x = [&](int ic) {
#pragma unroll
        for (int j = 0; j < 17; ++j) {
            int u = tid + NTH * j;
            if (u < ICH * XT) {
                int i  = u / XT;
                int tl = u - i * XT;
                int t  = tb + tl - 2;
                t = (t < 0) ? -t : ((t >= TLEN) ? (2 * TLEN - 2 - t) : t);
                xr[j] = ldg_f32(xb + (size_t)(ic + i) * TLEN + t);
            }
        }
    };
    // ---- convert + store x regs into stage st ----
    auto store_x = [&](int st) {
#pragma unroll
        for (int j = 0; j < 17; ++j) {
            int u = tid + NTH * j;
            if (u < ICH * XT) {
                int i  = u / XT;
                int tl = u - i * XT;
                xs[st * XS_ST + tl * XR + i] = __float2half_rn(xr[j]);
            }
        }
    };

    // ---- prologue: fill stage 0 ----
    prefetch_w(0, 0);
    load_x(0);
    store_x(0);
    CP_WAIT0();
    __syncthreads();

    for (int c = 0; c < NCH; ++c) {
        const int st = c & 1;
        const int nst = st ^ 1;
        if (c + 1 < NCH) {
            prefetch_w((c + 1) * ICH, nst);
            load_x((c + 1) * ICH);
        }

        // ---- MMA over stage st ----
        const __half* wsp = ws + st * WS_ST;
        const __half* xsp = xs + st * XS_ST;

        for (int tap = 0; tap < KS; ++tap) {
#pragma unroll
            for (int k16 = 0; k16 < ICH; k16 += 16) {
                unsigned ah[2][4];
#pragma unroll
                for (int mt = 0; mt < 2; ++mt) {
                    int row = tap * OTI + wo * 32 + mt * 16 + lq;
                    int col = k16 + lr * 2;
                    const __half* ph = wsp + row * XR + col;
                    ah[mt][0] = lds32(ph);
                    ah[mt][1] = lds32(ph + 8 * XR);
                    ah[mt][2] = lds32(ph + 8);
                    ah[mt][3] = lds32(ph + 8 * XR + 8);
                }
#pragma unroll
                for (int nt = 0; nt < 8; ++nt) {
                    int trow = wt * 64 + nt * 8 + lq + tap;
                    int col  = k16 + lr * 2;
                    const __half* ph = xsp + trow * XR + col;
                    unsigned bh0 = lds32(ph), bh1 = lds32(ph + 8);
#pragma unroll
                    for (int mt = 0; mt < 2; ++mt)
                        mma16816(acc[mt][nt], ah[mt], bh0, bh1);
                }
            }
        }

        if (c + 1 < NCH) {
            store_x(nst);
            CP_WAIT0();
        }
        __syncthreads();
    }

    // ---- epilogue: leaky relu + store ----
#pragma unroll
    for (int mt = 0; mt < 2; ++mt) {
#pragma unroll
        for (int nt = 0; nt < 8; ++nt) {
            int o0 = ob + wo * 32 + mt * 16 + lq;
            int t0 = tb + wt * 64 + nt * 8 + lr * 2;
            float z0 = acc[mt][nt][0], z1 = acc[mt][nt][1];
            float z2 = acc[mt][nt][2], z3 = acc[mt][nt][3];
            z0 = (z0 > 0.f) ? z0 : 0.2f * z0;
            z1 = (z1 > 0.f) ? z1 : 0.2f * z1;
            z2 = (z2 > 0.f) ? z2 : 0.2f * z2;
            z3 = (z3 > 0.f) ? z3 : 0.2f * z3;
            float* p0 = out + ((size_t)b * COUT + o0) * TLEN + t0;
            *(float2*)p0 = make_float2(z0, z1);
            *(float2*)(p0 + 8 * TLEN) = make_float2(z2, z3);
        }
    }
}

// ---------------------------------------------------------------------------
extern "C" void kernel_launch(void* const* d_in, const int* in_sizes, int n_in,
                              void* d_out, int out_size) {
    const float* x       = (const float*)d_in[0];   // [16,256,8192]
    const float* c_trg   = (const float*)d_in[1];   // [16,128]
    const float* style_w = (const float*)d_in[2];   // [256,128]
    const float* style_b = (const float*)d_in[3];   // [256]
    const float* weight  = (const float*)d_in[4];   // [1,256,256,5]
    float* out = (float*)d_out;

    prep_kernel<<<NB, 256>>>(c_trg, style_w, style_b, weight);
    wm_kernel<<<(NB * KS * CIN * COUT) / 256, 256>>>(weight);

    static bool attr_done = false;
    if (!attr_done) {
        cudaFuncSetAttribute(conv_kernel,
                             cudaFuncAttributeMaxDynamicSharedMemorySize,
                             SMEM_BYTES);
        attr_done = true;
    }
    dim3 grid(TLEN / TTI, COUT / OTI, NB);        // (32, 2, 16)
    conv_kernel<<<grid, NTH, SMEM_BYTES>>>(x, out);

    size_t conv_elems = (size_t)NB * COUT * TLEN;
    if ((size_t)out_size > conv_elems) {
        cudaMemcpyAsync(out + conv_elems, c_trg,
                        (out_size - conv_elems) * sizeof(float),
                        cudaMemcpyDeviceToDevice);
    }
}

// round 12
// speedup vs baseline: 1.5233x; 1.4306x over previous
#include <cuda_runtime.h>
#include <cuda_fp16.h>
#include <cstdint>

#define NB   16
#define CIN  256
#define COUT 256
#define KS   5
#define SPK  128
#define TLEN 8192

#define OTI  128     // o tile per block (4 o-warps)
#define TTI  256     // t tile per block (4 t-warps)
#define ICH  32      // i chunk
#define XR   40      // padded row pitch (80B -> 16B-aligned quarters)
#define XT   260     // xs rows (t range: tile + 4 pad)
#define NCH  8       // CIN / ICH
#define NTH  512

#define XS_ST (XT * XR)              // 10400 elems per stage
#define WS_ST (KS * OTI * XR)        // 25600 elems per stage
#define SMEM_BYTES ((2 * XS_ST + 2 * WS_ST) * 2)   // 144000

// scratch (no cudaMalloc allowed)
__device__ float g_s[NB * CIN];
__device__ float g_demod[NB * COUT];
__device__ float g_wsqT[CIN * COUT];                         // [i][o]
__device__ __half g_wm[(size_t)NB * KS * COUT * CIN];        // [b][k][o][i]

// ---------------------------------------------------------------------------
__global__ void style_kernel(const float* __restrict__ c_trg,
                             const float* __restrict__ style_w,
                             const float* __restrict__ style_b) {
    int b = blockIdx.x;
    int i = threadIdx.x;
    const float* c = c_trg + b * SPK;
    const float* w = style_w + i * SPK;
    float acc = 0.f;
#pragma unroll 8
    for (int j = 0; j < SPK; ++j) acc += c[j] * w[j];
    g_s[b * CIN + i] = acc + style_b[i];
}

__global__ void wsq_kernel(const float* __restrict__ weight) {
    int i = blockIdx.x;
    int o = threadIdx.x;
    const float* wp = weight + ((size_t)o * CIN + i) * KS;
    float acc = 0.f;
#pragma unroll
    for (int k = 0; k < KS; ++k) acc += wp[k] * wp[k];
    g_wsqT[i * COUT + o] = acc;
}

__global__ void demod_kernel() {
    int b = blockIdx.x;
    int o = threadIdx.x;
    const float* sp = g_s + b * CIN;
    float acc = 0.f;
#pragma unroll 4
    for (int i = 0; i < CIN; ++i) {
        float s = sp[i];
        acc += s * s * g_wsqT[i * COUT + o];
    }
    g_demod[b * COUT + o] = rsqrtf(acc + 1e-8f);
}

// g_wm[b][k][o][i] = fp16( weight[o,i,k]*s[b,i]*demod[b,o] )
__global__ void wm_kernel(const float* __restrict__ weight) {
    int idx = blockIdx.x * blockDim.x + threadIdx.x;   // NB*KS*COUT*CIN
    int i = idx & (CIN - 1);
    int o = (idx >> 8) & (COUT - 1);
    int kb = idx >> 16;
    int k = kb % KS;
    int b = kb / KS;
    float wv = weight[((size_t)o * CIN + i) * KS + k]
             * g_s[b * CIN + i] * g_demod[b * COUT + o];
    g_wm[idx] = __float2half_rn(wv);
}

// ---------------------------------------------------------------------------
__device__ __forceinline__ void mma16816(float* d, const unsigned* a,
                                         unsigned b0, unsigned b1) {
    asm volatile(
        "mma.sync.aligned.m16n8k16.row.col.f32.f16.f16.f32 "
        "{%0,%1,%2,%3}, {%4,%5,%6,%7}, {%8,%9}, {%0,%1,%2,%3};"
        : "+f"(d[0]), "+f"(d[1]), "+f"(d[2]), "+f"(d[3])
        : "r"(a[0]), "r"(a[1]), "r"(a[2]), "r"(a[3]), "r"(b0), "r"(b1));
}
__device__ __forceinline__ unsigned lds32(const __half* p) {
    return *(const unsigned*)p;
}
__device__ __forceinline__ uint32_t smem_u32(const void* p) {
    uint32_t a;
    asm("{ .reg .u64 t; cvta.to.shared.u64 t, %1; cvt.u32.u64 %0, t; }"
        : "=r"(a) : "l"(p));
    return a;
}
__device__ __forceinline__ void cp16(uint32_t dst, const void* src) {
    asm volatile("cp.async.cg.shared.global [%0], [%1], 16;"
                 :: "r"(dst), "l"(src));
}
#define CP_COMMIT() asm volatile("cp.async.commit_group;" ::: "memory")
#define CP_WAIT0()  asm volatile("cp.async.wait_group 0;" ::: "memory")

__device__ __forceinline__ float ldg_f32(const float* p) {
    float v;
    asm volatile("ld.global.nc.f32 %0, [%1];" : "=f"(v) : "l"(p));
    return v;
}

// ---------------------------------------------------------------------------
// Main conv: out[b,o,t] = leaky( sum_{i,k} Wm[b,o,i,k] * x_reflpad[b,i,t+k] )
// fp16 mma.sync, 512 threads = 128o x 256t per CTA, double-buffered smem.
__global__ __launch_bounds__(NTH, 1)
void conv_kernel(const float* __restrict__ x, float* __restrict__ out) {
    extern __shared__ __align__(16) __half sm[];
    __half* xs = sm;                        // [2][XS_ST]
    __half* ws = sm + 2 * XS_ST;            // [2][WS_ST]
    const uint32_t ws_a = smem_u32(ws);

    const int b  = blockIdx.z;
    const int ob = blockIdx.y * OTI;
    const int tb = blockIdx.x * TTI;
    const int tid = threadIdx.x;
    const int wid = tid >> 5;
    const int lane = tid & 31;
    const int wo = wid & 3;           // o warp (4): 32 o each
    const int wt = wid >> 2;          // t warp (4): 64 t each
    const int lq = lane >> 2;
    const int lr = lane & 3;

    float acc[2][8][4];
#pragma unroll
    for (int mt = 0; mt < 2; ++mt)
#pragma unroll
        for (int nt = 0; nt < 8; ++nt)
#pragma unroll
            for (int e = 0; e < 4; ++e) acc[mt][nt][e] = 0.f;

    const float* xb = x + (size_t)b * CIN * TLEN;
    const __half* wmb = g_wm + (size_t)b * KS * COUT * CIN;

    float xr[17];

    // ---- prefetch Ws: 640 rows x 4 aligned 16B chunks = 2560 cp16 ----
    auto prefetch_w = [&](int ic, int st) {
#pragma unroll
        for (int m = 0; m < 5; ++m) {
            int v = tid + NTH * m;                  // < 2560
            int row = v >> 2;                        // k*OTI + o  (0..639)
            int c4  = v & 3;
            int k = row >> 7;
            int o = row & 127;
            const __half* src =
                wmb + ((size_t)(k * COUT + ob + o) * CIN + ic) + c4 * 8;
            uint32_t dst = ws_a + (uint32_t)(st * WS_ST + row * XR) * 2 + c4 * 16;
            cp16(dst, src);
        }
        CP_COMMIT();
    };
    // ---- issue x LDGs for chunk into regs (latency hidden under MMAs) ----
    auto load_x = [&](int ic) {
#pragma unroll
        for (int j = 0; j < 17; ++j) {
            int u = tid + NTH * j;
            if (u < ICH * XT) {
                int i  = u / XT;
                int tl = u - i * XT;
                int t  = tb + tl - 2;
                t = (t < 0) ? -t : ((t >= TLEN) ? (2 * TLEN - 2 - t) : t);
                xr[j] = ldg_f32(xb + (size_t)(ic + i) * TLEN + t);
            }
        }
    };
    // ---- convert + store x regs into stage st ----
    auto store_x = [&](int st) {
#pragma unroll
        for (int j = 0; j < 17; ++j) {
            int u = tid + NTH * j;
            if (u < ICH * XT) {
                int i  = u / XT;
                int tl = u - i * XT;
                xs[st * XS_ST + tl * XR + i] = __float2half_rn(xr[j]);
            }
        }
    };

    // ---- prologue: fill stage 0 ----
    prefetch_w(0, 0);
    load_x(0);
    store_x(0);
    CP_WAIT0();
    __syncthreads();

    for (int c = 0; c < NCH; ++c) {
        const int st = c & 1;
        const int nst = st ^ 1;
        if (c + 1 < NCH) {
            prefetch_w((c + 1) * ICH, nst);
            load_x((c + 1) * ICH);
        }

        // ---- MMA over stage st ----
        const __half* wsp = ws + st * WS_ST;
        const __half* xsp = xs + st * XS_ST;

        for (int tap = 0; tap < KS; ++tap) {
#pragma unroll
            for (int k16 = 0; k16 < ICH; k16 += 16) {
                unsigned ah[2][4];
#pragma unroll
                for (int mt = 0; mt < 2; ++mt) {
                    int row = tap * OTI + wo * 32 + mt * 16 + lq;
                    int col = k16 + lr * 2;
                    const __half* ph = wsp + row * XR + col;
                    ah[mt][0] = lds32(ph);
                    ah[mt][1] = lds32(ph + 8 * XR);
                    ah[mt][2] = lds32(ph + 8);
                    ah[mt][3] = lds32(ph + 8 * XR + 8);
                }
#pragma unroll
                for (int nt = 0; nt < 8; ++nt) {
                    int trow = wt * 64 + nt * 8 + lq + tap;
                    int col  = k16 + lr * 2;
                    const __half* ph = xsp + trow * XR + col;
                    unsigned bh0 = lds32(ph), bh1 = lds32(ph + 8);
#pragma unroll
                    for (int mt = 0; mt < 2; ++mt)
                        mma16816(acc[mt][nt], ah[mt], bh0, bh1);
                }
            }
        }

        if (c + 1 < NCH) {
            store_x(nst);
            CP_WAIT0();
        }
        __syncthreads();
    }

    // ---- epilogue: leaky relu + store ----
#pragma unroll
    for (int mt = 0; mt < 2; ++mt) {
#pragma unroll
        for (int nt = 0; nt < 8; ++nt) {
            int o0 = ob + wo * 32 + mt * 16 + lq;
            int t0 = tb + wt * 64 + nt * 8 + lr * 2;
            float z0 = acc[mt][nt][0], z1 = acc[mt][nt][1];
            float z2 = acc[mt][nt][2], z3 = acc[mt][nt][3];
            z0 = (z0 > 0.f) ? z0 : 0.2f * z0;
            z1 = (z1 > 0.f) ? z1 : 0.2f * z1;
            z2 = (z2 > 0.f) ? z2 : 0.2f * z2;
            z3 = (z3 > 0.f) ? z3 : 0.2f * z3;
            float* p0 = out + ((size_t)b * COUT + o0) * TLEN + t0;
            *(float2*)p0 = make_float2(z0, z1);
            *(float2*)(p0 + 8 * TLEN) = make_float2(z2, z3);
        }
    }
}

// ---------------------------------------------------------------------------
extern "C" void kernel_launch(void* const* d_in, const int* in_sizes, int n_in,
                              void* d_out, int out_size) {
    const float* x       = (const float*)d_in[0];   // [16,256,8192]
    const float* c_trg   = (const float*)d_in[1];   // [16,128]
    const float* style_w = (const float*)d_in[2];   // [256,128]
    const float* style_b = (const float*)d_in[3];   // [256]
    const float* weight  = (const float*)d_in[4];   // [1,256,256,5]
    float* out = (float*)d_out;

    style_kernel<<<NB, CIN>>>(c_trg, style_w, style_b);
    wsq_kernel<<<CIN, COUT>>>(weight);
    demod_kernel<<<NB, COUT>>>();
    wm_kernel<<<(NB * KS * CIN * COUT) / 256, 256>>>(weight);

    static bool attr_done = false;
    if (!attr_done) {
        cudaFuncSetAttribute(conv_kernel,
                             cudaFuncAttributeMaxDynamicSharedMemorySize,
                             SMEM_BYTES);
        attr_done = true;
    }
    dim3 grid(TLEN / TTI, COUT / OTI, NB);        // (32, 2, 16)
    conv_kernel<<<grid, NTH, SMEM_BYTES>>>(x, out);

    size_t conv_elems = (size_t)NB * COUT * TLEN;
    if ((size_t)out_size > conv_elems) {
        cudaMemcpyAsync(out + conv_elems, c_trg,
                        (out_size - conv_elems) * sizeof(float),
                        cudaMemcpyDeviceToDevice);
    }
}

// round 13
// speedup vs baseline: 1.6450x; 1.0799x over previous
#include <cuda_runtime.h>
#include <cuda_fp16.h>
#include <cstdint>

#define NB   16
#define CIN  256
#define COUT 256
#define KS   5
#define SPK  128
#define TLEN 8192

#define OTI  128     // o tile per block (4 o-warps)
#define TTI  256     // t tile per block (4 t-warps)
#define ICH  32      // i chunk
#define XR   40      // padded row pitch (80B -> 16B-aligned quarters)
#define XT   260     // xs rows (t range: tile + 4 pad)
#define NCH  8       // CIN / ICH
#define NTH  512

#define XS_ST (XT * XR)              // 10400 elems per stage
#define WS_ST (KS * OTI * XR)        // 25600 elems per stage
#define SMEM_BYTES ((2 * XS_ST + 2 * WS_ST) * 2)   // 144000

// scratch (no cudaMalloc allowed)
__device__ float g_s[NB * CIN];
__device__ __half g_wm[(size_t)NB * KS * COUT * CIN];        // [b][k][o][i]

// ---------------------------------------------------------------------------
__global__ void style_kernel(const float* __restrict__ c_trg,
                             const float* __restrict__ style_w,
                             const float* __restrict__ style_b) {
    int b = blockIdx.x;
    int i = threadIdx.x;
    const float* c = c_trg + b * SPK;
    const float* w = style_w + i * SPK;
    float acc = 0.f;
#pragma unroll 8
    for (int j = 0; j < SPK; ++j) acc += c[j] * w[j];
    g_s[b * CIN + i] = acc + style_b[i];
}

// Fused wsq + demod + wm. Block = (b, o), thread = i.
// demod = rsqrt( sum_i s[b,i]^2 * sum_k w[o,i,k]^2 + 1e-8 )
// g_wm[b][k][o][i] = fp16( w[o,i,k] * s[b,i] * demod )
__global__ __launch_bounds__(256)
void wmfused_kernel(const float* __restrict__ weight) {
    __shared__ float red[8];
    int bo = blockIdx.x;
    int b = bo >> 8;
    int o = bo & 255;
    int i = threadIdx.x;
    int lane = i & 31;
    int wrp = i >> 5;

    const float* wp = weight + ((size_t)o * CIN + i) * KS;
    float w0 = wp[0], w1 = wp[1], w2 = wp[2], w3 = wp[3], w4 = wp[4];
    float s = g_s[b * CIN + i];
    float part = s * s * (w0 * w0 + w1 * w1 + w2 * w2 + w3 * w3 + w4 * w4);

    // warp reduce
#pragma unroll
    for (int d = 16; d > 0; d >>= 1)
        part += __shfl_xor_sync(0xFFFFFFFFu, part, d);
    if (lane == 0) red[wrp] = part;
    __syncthreads();
    float tot = red[lane & 7];
#pragma unroll
    for (int d = 4; d > 0; d >>= 1)
        tot += __shfl_xor_sync(0xFFFFFFFFu, tot, d);
    // every thread now has (a lane-dependent but) full sum for d covering 8 slots:
    // lanes 0..7 cycle; after xor-reduce over 3 levels all 8 values summed.
    float demod = rsqrtf(tot + 1e-8f);

    float sd = s * demod;
    __half* dst = g_wm + ((size_t)b * KS * COUT + o) * CIN + i;
#pragma unroll
    for (int k = 0; k < KS; ++k) {
        float wv = wp[k] * sd;
        dst[(size_t)k * COUT * CIN] = __float2half_rn(wv);
    }
}

// ---------------------------------------------------------------------------
__device__ __forceinline__ void mma16816(float* d, const unsigned* a,
                                         unsigned b0, unsigned b1) {
    asm volatile(
        "mma.sync.aligned.m16n8k16.row.col.f32.f16.f16.f32 "
        "{%0,%1,%2,%3}, {%4,%5,%6,%7}, {%8,%9}, {%0,%1,%2,%3};"
        : "+f"(d[0]), "+f"(d[1]), "+f"(d[2]), "+f"(d[3])
        : "r"(a[0]), "r"(a[1]), "r"(a[2]), "r"(a[3]), "r"(b0), "r"(b1));
}
__device__ __forceinline__ unsigned lds32(const __half* p) {
    return *(const unsigned*)p;
}
__device__ __forceinline__ uint32_t smem_u32(const void* p) {
    uint32_t a;
    asm("{ .reg .u64 t; cvta.to.shared.u64 t, %1; cvt.u32.u64 %0, t; }"
        : "=r"(a) : "l"(p));
    return a;
}
__device__ __forceinline__ void cp16(uint32_t dst, const void* src) {
    asm volatile("cp.async.cg.shared.global [%0], [%1], 16;"
                 :: "r"(dst), "l"(src));
}
#define CP_COMMIT() asm volatile("cp.async.commit_group;" ::: "memory")
#define CP_WAIT0()  asm volatile("cp.async.wait_group 0;" ::: "memory")

__device__ __forceinline__ float ldg_f32(const float* p) {
    float v;
    asm volatile("ld.global.nc.f32 %0, [%1];" : "=f"(v) : "l"(p));
    return v;
}

// ---------------------------------------------------------------------------
// Main conv: out[b,o,t] = leaky( sum_{i,k} Wm[b,o,i,k] * x_reflpad[b,i,t+k] )
// fp16 mma.sync, 512 threads = 128o x 256t per CTA, double-buffered smem.
__global__ __launch_bounds__(NTH, 1)
void conv_kernel(const float* __restrict__ x, float* __restrict__ out) {
    extern __shared__ __align__(16) __half sm[];
    __half* xs = sm;                        // [2][XS_ST]
    __half* ws = sm + 2 * XS_ST;            // [2][WS_ST]
    const uint32_t ws_a = smem_u32(ws);

    const int b  = blockIdx.z;
    const int ob = blockIdx.y * OTI;
    const int tb = blockIdx.x * TTI;
    const int tid = threadIdx.x;
    const int wid = tid >> 5;
    const int lane = tid & 31;
    const int wo = wid & 3;           // o warp (4): 32 o each
    const int wt = wid >> 2;          // t warp (4): 64 t each
    const int lq = lane >> 2;
    const int lr = lane & 3;

    float acc[2][8][4];
#pragma unroll
    for (int mt = 0; mt < 2; ++mt)
#pragma unroll
        for (int nt = 0; nt < 8; ++nt)
#pragma unroll
            for (int e = 0; e < 4; ++e) acc[mt][nt][e] = 0.f;

    const float* xb = x + (size_t)b * CIN * TLEN;
    const __half* wmb = g_wm + (size_t)b * KS * COUT * CIN;

    float xr[17];

    // ---- prefetch Ws: 640 rows x 4 aligned 16B chunks = 2560 cp16 ----
    auto prefetch_w = [&](int ic, int st) {
#pragma unroll
        for (int m = 0; m < 5; ++m) {
            int v = tid + NTH * m;                  // < 2560
            int row = v >> 2;                        // k*OTI + o  (0..639)
            int c4  = v & 3;
            int k = row >> 7;
            int o = row & 127;
            const __half* src =
                wmb + ((size_t)(k * COUT + ob + o) * CIN + ic) + c4 * 8;
            uint32_t dst = ws_a + (uint32_t)(st * WS_ST + row * XR) * 2 + c4 * 16;
            cp16(dst, src);
        }
        CP_COMMIT();
    };
    // ---- issue x LDGs for chunk into regs (latency hidden under MMAs) ----
    auto load_x = [&](int ic) {
#pragma unroll
        for (int j = 0; j < 17; ++j) {
            int u = tid + NTH * j;
            if (u < ICH * XT) {
                int i  = u / XT;
                int tl = u - i * XT;
                int t  = tb + tl - 2;
                t = (t < 0) ? -t : ((t >= TLEN) ? (2 * TLEN - 2 - t) : t);
                xr[j] = ldg_f32(xb + (size_t)(ic + i) * TLEN + t);
            }
        }
    };
    // ---- convert + store x regs into stage st ----
    auto store_x = [&](int st) {
#pragma unroll
        for (int j = 0; j < 17; ++j) {
            int u = tid + NTH * j;
            if (u < ICH * XT) {
                int i  = u / XT;
                int tl = u - i * XT;
                xs[st * XS_ST + tl * XR + i] = __float2half_rn(xr[j]);
            }
        }
    };

    // ---- prologue: fill stage 0 ----
    prefetch_w(0, 0);
    load_x(0);
    store_x(0);
    CP_WAIT0();
    __syncthreads();

    for (int c = 0; c < NCH; ++c) {
        const int st = c & 1;
        const int nst = st ^ 1;
        if (c + 1 < NCH) {
            prefetch_w((c + 1) * ICH, nst);
            load_x((c + 1) * ICH);
        }

        // ---- MMA over stage st ----
        const __half* wsp = ws + st * WS_ST;
        const __half* xsp = xs + st * XS_ST;

        for (int tap = 0; tap < KS; ++tap) {
#pragma unroll
            for (int k16 = 0; k16 < ICH; k16 += 16) {
                unsigned ah[2][4];
#pragma unroll
                for (int mt = 0; mt < 2; ++mt) {
                    int row = tap * OTI + wo * 32 + mt * 16 + lq;
                    int col = k16 + lr * 2;
                    const __half* ph = wsp + row * XR + col;
                    ah[mt][0] = lds32(ph);
                    ah[mt][1] = lds32(ph + 8 * XR);
                    ah[mt][2] = lds32(ph + 8);
                    ah[mt][3] = lds32(ph + 8 * XR + 8);
                }
#pragma unroll
                for (int nt = 0; nt < 8; ++nt) {
                    int trow = wt * 64 + nt * 8 + lq + tap;
                    int col  = k16 + lr * 2;
                    const __half* ph = xsp + trow * XR + col;
                    unsigned bh0 = lds32(ph), bh1 = lds32(ph + 8);
#pragma unroll
                    for (int mt = 0; mt < 2; ++mt)
                        mma16816(acc[mt][nt], ah[mt], bh0, bh1);
                }
            }
        }

        if (c + 1 < NCH) {
            store_x(nst);
            CP_WAIT0();
        }
        __syncthreads();
    }

    // ---- epilogue: leaky relu + store ----
#pragma unroll
    for (int mt = 0; mt < 2; ++mt) {
#pragma unroll
        for (int nt = 0; nt < 8; ++nt) {
            int o0 = ob + wo * 32 + mt * 16 + lq;
            int t0 = tb + wt * 64 + nt * 8 + lr * 2;
            float z0 = acc[mt][nt][0], z1 = acc[mt][nt][1];
            float z2 = acc[mt][nt][2], z3 = acc[mt][nt][3];
            z0 = (z0 > 0.f) ? z0 : 0.2f * z0;
            z1 = (z1 > 0.f) ? z1 : 0.2f * z1;
            z2 = (z2 > 0.f) ? z2 : 0.2f * z2;
            z3 = (z3 > 0.f) ? z3 : 0.2f * z3;
            float* p0 = out + ((size_t)b * COUT + o0) * TLEN + t0;
            *(float2*)p0 = make_float2(z0, z1);
            *(float2*)(p0 + 8 * TLEN) = make_float2(z2, z3);
        }
    }
}

// ---------------------------------------------------------------------------
extern "C" void kernel_launch(void* const* d_in, const int* in_sizes, int n_in,
                              void* d_out, int out_size) {
    const float* x       = (const float*)d_in[0];   // [16,256,8192]
    const float* c_trg   = (const float*)d_in[1];   // [16,128]
    const float* style_w = (const float*)d_in[2];   // [256,128]
    const float* style_b = (const float*)d_in[3];   // [256]
    const float* weight  = (const float*)d_in[4];   // [1,256,256,5]
    float* out = (float*)d_out;

    style_kernel<<<NB, CIN>>>(c_trg, style_w, style_b);
    wmfused_kernel<<<NB * COUT, 256>>>(weight);

    static bool attr_done = false;
    if (!attr_done) {
        cudaFuncSetAttribute(conv_kernel,
                             cudaFuncAttributeMaxDynamicSharedMemorySize,
                             SMEM_BYTES);
        attr_done = true;
    }
    dim3 grid(TLEN / TTI, COUT / OTI, NB);        // (32, 2, 16)
    conv_kernel<<<grid, NTH, SMEM_BYTES>>>(x, out);

    size_t conv_elems = (size_t)NB * COUT * TLEN;
    if ((size_t)out_size > conv_elems) {
        cudaMemcpyAsync(out + conv_elems, c_trg,
                        (out_size - conv_elems) * sizeof(float),
                        cudaMemcpyDeviceToDevice);
    }
}

// round 14
// speedup vs baseline: 1.7318x; 1.0528x over previous
#include <cuda_runtime.h>
#include <cuda_fp16.h>
#include <cstdint>

#define NB   16
#define CIN  256
#define COUT 256
#define KS   5
#define SPK  128
#define TLEN 8192

#define OTI  128     // o tile per block (4 o-warps)
#define TTI  256     // t tile per block (4 t-warps)
#define ICH  32      // i chunk
#define XR   40      // padded row pitch (80B -> 16B-aligned quarters)
#define XT   260     // xs rows (t range: tile + 4 pad)
#define NCH  8       // CIN / ICH
#define NTH  512

#define XS_ST (XT * XR)              // 10400 elems per stage
#define WS_ST (KS * OTI * XR)        // 25600 elems per stage
#define SMEM_BYTES ((2 * XS_ST + 2 * WS_ST) * 2)   // 144000

// scratch (no cudaMalloc allowed)
__device__ float g_s[NB * CIN];
__device__ __half g_wm[(size_t)NB * KS * COUT * CIN];        // [b][k][o][i]

// ---------------------------------------------------------------------------
// style GEMV, one warp per (b, i): s[b,i] = dot(c_trg[b,:], style_w[i,:]) + bias
__global__ __launch_bounds__(256)
void style_kernel(const float* __restrict__ c_trg,
                  const float* __restrict__ style_w,
                  const float* __restrict__ style_b) {
    int v = blockIdx.x * 8 + (threadIdx.x >> 5);   // warp index: b*CIN + i
    int lane = threadIdx.x & 31;
    int b = v >> 8;
    int i = v & 255;
    const float* c = c_trg + b * SPK;
    const float* w = style_w + i * SPK;
    float acc = 0.f;
#pragma unroll
    for (int j = 0; j < 4; ++j) {
        int idx = lane + j * 32;
        acc += c[idx] * w[idx];
    }
#pragma unroll
    for (int d = 16; d > 0; d >>= 1)
        acc += __shfl_xor_sync(0xFFFFFFFFu, acc, d);
    if (lane == 0) g_s[v] = acc + style_b[i];
}

// Fused wsq + demod + wm. Block = (b, o), thread = i.
// demod = rsqrt( sum_i s[b,i]^2 * sum_k w[o,i,k]^2 + 1e-8 )
// g_wm[b][k][o][i] = fp16( w[o,i,k] * s[b,i] * demod )
__global__ __launch_bounds__(256)
void wmfused_kernel(const float* __restrict__ weight) {
    __shared__ float red[8];
    int bo = blockIdx.x;
    int b = bo >> 8;
    int o = bo & 255;
    int i = threadIdx.x;
    int lane = i & 31;
    int wrp = i >> 5;

    const float* wp = weight + ((size_t)o * CIN + i) * KS;
    float w0 = wp[0], w1 = wp[1], w2 = wp[2], w3 = wp[3], w4 = wp[4];
    float s = g_s[b * CIN + i];
    float part = s * s * (w0 * w0 + w1 * w1 + w2 * w2 + w3 * w3 + w4 * w4);

    // warp reduce
#pragma unroll
    for (int d = 16; d > 0; d >>= 1)
        part += __shfl_xor_sync(0xFFFFFFFFu, part, d);
    if (lane == 0) red[wrp] = part;
    __syncthreads();
    float tot = red[lane & 7];
#pragma unroll
    for (int d = 4; d > 0; d >>= 1)
        tot += __shfl_xor_sync(0xFFFFFFFFu, tot, d);
    float demod = rsqrtf(tot + 1e-8f);

    float sd = s * demod;
    __half* dst = g_wm + ((size_t)b * KS * COUT + o) * CIN + i;
#pragma unroll
    for (int k = 0; k < KS; ++k) {
        float wv = wp[k] * sd;
        dst[(size_t)k * COUT * CIN] = __float2half_rn(wv);
    }
}

// ---------------------------------------------------------------------------
__device__ __forceinline__ void mma16816(float* d, const unsigned* a,
                                         unsigned b0, unsigned b1) {
    asm volatile(
        "mma.sync.aligned.m16n8k16.row.col.f32.f16.f16.f32 "
        "{%0,%1,%2,%3}, {%4,%5,%6,%7}, {%8,%9}, {%0,%1,%2,%3};"
        : "+f"(d[0]), "+f"(d[1]), "+f"(d[2]), "+f"(d[3])
        : "r"(a[0]), "r"(a[1]), "r"(a[2]), "r"(a[3]), "r"(b0), "r"(b1));
}
__device__ __forceinline__ unsigned lds32(const __half* p) {
    return *(const unsigned*)p;
}
__device__ __forceinline__ uint32_t smem_u32(const void* p) {
    uint32_t a;
    asm("{ .reg .u64 t; cvta.to.shared.u64 t, %1; cvt.u32.u64 %0, t; }"
        : "=r"(a) : "l"(p));
    return a;
}
__device__ __forceinline__ void cp16(uint32_t dst, const void* src) {
    asm volatile("cp.async.cg.shared.global [%0], [%1], 16;"
                 :: "r"(dst), "l"(src));
}
#define CP_COMMIT() asm volatile("cp.async.commit_group;" ::: "memory")
#define CP_WAIT0()  asm volatile("cp.async.wait_group 0;" ::: "memory")

__device__ __forceinline__ float ldg_f32(const float* p) {
    float v;
    asm volatile("ld.global.nc.f32 %0, [%1];" : "=f"(v) : "l"(p));
    return v;
}

// ---------------------------------------------------------------------------
// Main conv: out[b,o,t] = leaky( sum_{i,k} Wm[b,o,i,k] * x_reflpad[b,i,t+k] )
// fp16 mma.sync, 512 threads = 128o x 256t per CTA, double-buffered smem.
__global__ __launch_bounds__(NTH, 1)
void conv_kernel(const float* __restrict__ x, float* __restrict__ out) {
    extern __shared__ __align__(16) __half sm[];
    __half* xs = sm;                        // [2][XS_ST]
    __half* ws = sm + 2 * XS_ST;            // [2][WS_ST]
    const uint32_t ws_a = smem_u32(ws);

    const int b  = blockIdx.z;
    const int ob = blockIdx.y * OTI;
    const int tb = blockIdx.x * TTI;
    const int tid = threadIdx.x;
    const int wid = tid >> 5;
    const int lane = tid & 31;
    const int wo = wid & 3;           // o warp (4): 32 o each
    const int wt = wid >> 2;          // t warp (4): 64 t each
    const int lq = lane >> 2;
    const int lr = lane & 3;

    float acc[2][8][4];
#pragma unroll
    for (int mt = 0; mt < 2; ++mt)
#pragma unroll
        for (int nt = 0; nt < 8; ++nt)
#pragma unroll
            for (int e = 0; e < 4; ++e) acc[mt][nt][e] = 0.f;

    const float* xb = x + (size_t)b * CIN * TLEN;
    const __half* wmb = g_wm + (size_t)b * KS * COUT * CIN;

    float xr[17];

    // ---- prefetch Ws: 640 rows x 4 aligned 16B chunks = 2560 cp16 ----
    auto prefetch_w = [&](int ic, int st) {
#pragma unroll
        for (int m = 0; m < 5; ++m) {
            int v = tid + NTH * m;                  // < 2560
            int row = v >> 2;                        // k*OTI + o  (0..639)
            int c4  = v & 3;
            int k = row >> 7;
            int o = row & 127;
            const __half* src =
                wmb + ((size_t)(k * COUT + ob + o) * CIN + ic) + c4 * 8;
            uint32_t dst = ws_a + (uint32_t)(st * WS_ST + row * XR) * 2 + c4 * 16;
            cp16(dst, src);
        }
        CP_COMMIT();
    };
    // ---- issue x LDGs for chunk into regs (latency hidden under MMAs) ----
    auto load_x = [&](int ic) {
#pragma unroll
        for (int j = 0; j < 17; ++j) {
            int u = tid + NTH * j;
            if (u < ICH * XT) {
                int i  = u / XT;
                int tl = u - i * XT;
                int t  = tb + tl - 2;
                t = (t < 0) ? -t : ((t >= TLEN) ? (2 * TLEN - 2 - t) : t);
                xr[j] = ldg_f32(xb + (size_t)(ic + i) * TLEN + t);
            }
        }
    };
    // ---- convert + store x regs into stage st ----
    auto store_x = [&](int st) {
#pragma unroll
        for (int j = 0; j < 17; ++j) {
            int u = tid + NTH * j;
            if (u < ICH * XT) {
                int i  = u / XT;
                int tl = u - i * XT;
                xs[st * XS_ST + tl * XR + i] = __float2half_rn(xr[j]);
            }
        }
    };

    // ---- prologue: fill stage 0 ----
    prefetch_w(0, 0);
    load_x(0);
    store_x(0);
    CP_WAIT0();
    __syncthreads();

    for (int c = 0; c < NCH; ++c) {
        const int st = c & 1;
        const int nst = st ^ 1;
        if (c + 1 < NCH) {
            prefetch_w((c + 1) * ICH, nst);
            load_x((c + 1) * ICH);
        }

        // ---- MMA over stage st ----
        const __half* wsp = ws + st * WS_ST;
        const __half* xsp = xs + st * XS_ST;

        for (int tap = 0; tap < KS; ++tap) {
#pragma unroll
            for (int k16 = 0; k16 < ICH; k16 += 16) {
                unsigned ah[2][4];
#pragma unroll
                for (int mt = 0; mt < 2; ++mt) {
                    int row = tap * OTI + wo * 32 + mt * 16 + lq;
                    int col = k16 + lr * 2;
                    const __half* ph = wsp + row * XR + col;
                    ah[mt][0] = lds32(ph);
                    ah[mt][1] = lds32(ph + 8 * XR);
                    ah[mt][2] = lds32(ph + 8);
                    ah[mt][3] = lds32(ph + 8 * XR + 8);
                }
#pragma unroll
                for (int nt = 0; nt < 8; ++nt) {
                    int trow = wt * 64 + nt * 8 + lq + tap;
                    int col  = k16 + lr * 2;
                    const __half* ph = xsp + trow * XR + col;
                    unsigned bh0 = lds32(ph), bh1 = lds32(ph + 8);
#pragma unroll
                    for (int mt = 0; mt < 2; ++mt)
                        mma16816(acc[mt][nt], ah[mt], bh0, bh1);
                }
            }
        }

        if (c + 1 < NCH) {
            store_x(nst);
            CP_WAIT0();
        }
        __syncthreads();
    }

    // ---- epilogue: leaky relu + store ----
#pragma unroll
    for (int mt = 0; mt < 2; ++mt) {
#pragma unroll
        for (int nt = 0; nt < 8; ++nt) {
            int o0 = ob + wo * 32 + mt * 16 + lq;
            int t0 = tb + wt * 64 + nt * 8 + lr * 2;
            float z0 = acc[mt][nt][0], z1 = acc[mt][nt][1];
            float z2 = acc[mt][nt][2], z3 = acc[mt][nt][3];
            z0 = (z0 > 0.f) ? z0 : 0.2f * z0;
            z1 = (z1 > 0.f) ? z1 : 0.2f * z1;
            z2 = (z2 > 0.f) ? z2 : 0.2f * z2;
            z3 = (z3 > 0.f) ? z3 : 0.2f * z3;
            float* p0 = out + ((size_t)b * COUT + o0) * TLEN + t0;
            *(float2*)p0 = make_float2(z0, z1);
            *(float2*)(p0 + 8 * TLEN) = make_float2(z2, z3);
        }
    }
}

// ---------------------------------------------------------------------------
extern "C" void kernel_launch(void* const* d_in, const int* in_sizes, int n_in,
                              void* d_out, int out_size) {
    const float* x       = (const float*)d_in[0];   // [16,256,8192]
    const float* c_trg   = (const float*)d_in[1];   // [16,128]
    const float* style_w = (const float*)d_in[2];   // [256,128]
    const float* style_b = (const float*)d_in[3];   // [256]
    const float* weight  = (const float*)d_in[4];   // [1,256,256,5]
    float* out = (float*)d_out;

    style_kernel<<<(NB * CIN) / 8, 256>>>(c_trg, style_w, style_b);
    wmfused_kernel<<<NB * COUT, 256>>>(weight);

    static bool attr_done = false;
    if (!attr_done) {
        cudaFuncSetAttribute(conv_kernel,
                             cudaFuncAttributeMaxDynamicSharedMemorySize,
                             SMEM_BYTES);
        attr_done = true;
    }
    dim3 grid(TLEN / TTI, COUT / OTI, NB);        // (32, 2, 16)
    conv_kernel<<<grid, NTH, SMEM_BYTES>>>(x, out);

    size_t conv_elems = (size_t)NB * COUT * TLEN;
    if ((size_t)out_size > conv_elems) {
        cudaMemcpyAsync(out + conv_elems, c_trg,
                        (out_size - conv_elems) * sizeof(float),
                        cudaMemcpyDeviceToDevice);
    }
}

// round 15
// speedup vs baseline: 1.7388x; 1.0040x over previous
#include <cuda_runtime.h>
#include <cuda_fp16.h>
#include <cstdint>

#define NB   16
#define CIN  256
#define COUT 256
#define KS   5
#define SPK  128
#define TLEN 8192

#define OTI  128     // o tile per block (4 o-warps)
#define TTI  256     // t tile per block (4 t-warps)
#define ICH  32      // i chunk
#define XR   40      // padded row pitch (80B -> 16B-aligned quarters)
#define XT   260     // xs rows (t range: tile + 4 pad)
#define NCH  8       // CIN / ICH
#define NTH  512

#define XS_ST (XT * XR)              // 10400 elems per stage
#define WS_ST (KS * OTI * XR)        // 25600 elems per stage
#define SMEM_BYTES ((2 * XS_ST + 2 * WS_ST) * 2)   // 144000

// scratch (no cudaMalloc allowed)
__device__ float g_s[NB * CIN];
__device__ __half g_wm[(size_t)NB * KS * COUT * CIN];        // [b][k][o][i]

// ---------------------------------------------------------------------------
// style GEMV, one warp per (b, i): s[b,i] = dot(c_trg[b,:], style_w[i,:]) + bias
// Block 0 additionally copies the c_trg passthrough tail of the output.
__global__ __launch_bounds__(256)
void style_kernel(const float* __restrict__ c_trg,
                  const float* __restrict__ style_w,
                  const float* __restrict__ style_b,
                  float* __restrict__ out_tail, int n_tail) {
    int v = blockIdx.x * 8 + (threadIdx.x >> 5);   // warp index: b*CIN + i
    int lane = threadIdx.x & 31;
    int b = v >> 8;
    int i = v & 255;
    const float* c = c_trg + b * SPK;
    const float* w = style_w + i * SPK;
    float acc = 0.f;
#pragma unroll
    for (int j = 0; j < 4; ++j) {
        int idx = lane + j * 32;
        acc += c[idx] * w[idx];
    }
#pragma unroll
    for (int d = 16; d > 0; d >>= 1)
        acc += __shfl_xor_sync(0xFFFFFFFFu, acc, d);
    if (lane == 0) g_s[v] = acc + style_b[i];

    // passthrough second output (block 0 only)
    if (blockIdx.x == 0) {
        for (int u = threadIdx.x; u < n_tail; u += 256)
            out_tail[u] = c_trg[u];
    }
}

// Fused wsq + demod + wm. Block = (b, o), thread = i.
// demod = rsqrt( sum_i s[b,i]^2 * sum_k w[o,i,k]^2 + 1e-8 )
// g_wm[b][k][o][i] = fp16( w[o,i,k] * s[b,i] * demod )
__global__ __launch_bounds__(256)
void wmfused_kernel(const float* __restrict__ weight) {
    __shared__ float wsm[CIN * KS];    // 1280 floats, this o's weights [i][k]
    __shared__ float red[8];
    int bo = blockIdx.x;
    int b = bo >> 8;
    int o = bo & 255;
    int i = threadIdx.x;
    int lane = i & 31;
    int wrp = i >> 5;

    // coalesced float4 stage of weight[o, :, :] (1280 floats = 320 float4)
    {
        const float4* src = (const float4*)(weight + (size_t)o * CIN * KS);
        float4* dst = (float4*)wsm;
        for (int u = threadIdx.x; u < (CIN * KS) / 4; u += 256)
            dst[u] = src[u];
    }
    __syncthreads();

    const float* wp = wsm + i * KS;    // stride 5: bank-conflict-free
    float w0 = wp[0], w1 = wp[1], w2 = wp[2], w3 = wp[3], w4 = wp[4];
    float s = g_s[b * CIN + i];
    float part = s * s * (w0 * w0 + w1 * w1 + w2 * w2 + w3 * w3 + w4 * w4);

    // warp reduce
#pragma unroll
    for (int d = 16; d > 0; d >>= 1)
        part += __shfl_xor_sync(0xFFFFFFFFu, part, d);
    if (lane == 0) red[wrp] = part;
    __syncthreads();
    float tot = red[lane & 7];
#pragma unroll
    for (int d = 4; d > 0; d >>= 1)
        tot += __shfl_xor_sync(0xFFFFFFFFu, tot, d);
    float demod = rsqrtf(tot + 1e-8f);

    float sd = s * demod;
    __half* dst = g_wm + ((size_t)b * KS * COUT + o) * CIN + i;
    dst[0 * (size_t)COUT * CIN] = __float2half_rn(w0 * sd);
    dst[1 * (size_t)COUT * CIN] = __float2half_rn(w1 * sd);
    dst[2 * (size_t)COUT * CIN] = __float2half_rn(w2 * sd);
    dst[3 * (size_t)COUT * CIN] = __float2half_rn(w3 * sd);
    dst[4 * (size_t)COUT * CIN] = __float2half_rn(w4 * sd);
}

// ---------------------------------------------------------------------------
__device__ __forceinline__ void mma16816(float* d, const unsigned* a,
                                         unsigned b0, unsigned b1) {
    asm volatile(
        "mma.sync.aligned.m16n8k16.row.col.f32.f16.f16.f32 "
        "{%0,%1,%2,%3}, {%4,%5,%6,%7}, {%8,%9}, {%0,%1,%2,%3};"
        : "+f"(d[0]), "+f"(d[1]), "+f"(d[2]), "+f"(d[3])
        : "r"(a[0]), "r"(a[1]), "r"(a[2]), "r"(a[3]), "r"(b0), "r"(b1));
}
__device__ __forceinline__ unsigned lds32(const __half* p) {
    return *(const unsigned*)p;
}
__device__ __forceinline__ uint32_t smem_u32(const void* p) {
    uint32_t a;
    asm("{ .reg .u64 t; cvta.to.shared.u64 t, %1; cvt.u32.u64 %0, t; }"
        : "=r"(a) : "l"(p));
    return a;
}
__device__ __forceinline__ void cp16(uint32_t dst, const void* src) {
    asm volatile("cp.async.cg.shared.global [%0], [%1], 16;"
                 :: "r"(dst), "l"(src));
}
#define CP_COMMIT() asm volatile("cp.async.commit_group;" ::: "memory")
#define CP_WAIT0()  asm volatile("cp.async.wait_group 0;" ::: "memory")

__device__ __forceinline__ float ldg_f32(const float* p) {
    float v;
    asm volatile("ld.global.nc.f32 %0, [%1];" : "=f"(v) : "l"(p));
    return v;
}

// ---------------------------------------------------------------------------
// Main conv: out[b,o,t] = leaky( sum_{i,k} Wm[b,o,i,k] * x_reflpad[b,i,t+k] )
// fp16 mma.sync, 512 threads = 128o x 256t per CTA, double-buffered smem.
__global__ __launch_bounds__(NTH, 1)
void conv_kernel(const float* __restrict__ x, float* __restrict__ out) {
    extern __shared__ __align__(16) __half sm[];
    __half* xs = sm;                        // [2][XS_ST]
    __half* ws = sm + 2 * XS_ST;            // [2][WS_ST]
    const uint32_t ws_a = smem_u32(ws);

    const int b  = blockIdx.z;
    const int ob = blockIdx.y * OTI;
    const int tb = blockIdx.x * TTI;
    const int tid = threadIdx.x;
    const int wid = tid >> 5;
    const int lane = tid & 31;
    const int wo = wid & 3;           // o warp (4): 32 o each
    const int wt = wid >> 2;          // t warp (4): 64 t each
    const int lq = lane >> 2;
    const int lr = lane & 3;

    float acc[2][8][4];
#pragma unroll
    for (int mt = 0; mt < 2; ++mt)
#pragma unroll
        for (int nt = 0; nt < 8; ++nt)
#pragma unroll
            for (int e = 0; e < 4; ++e) acc[mt][nt][e] = 0.f;

    const float* xb = x + (size_t)b * CIN * TLEN;
    const __half* wmb = g_wm + (size_t)b * KS * COUT * CIN;

    float xr[17];

    // ---- prefetch Ws: 640 rows x 4 aligned 16B chunks = 2560 cp16 ----
    auto prefetch_w = [&](int ic, int st) {
#pragma unroll
        for (int m = 0; m < 5; ++m) {
            int v = tid + NTH * m;                  // < 2560
            int row = v >> 2;                        // k*OTI + o  (0..639)
            int c4  = v & 3;
            int k = row >> 7;
            int o = row & 127;
            const __half* src =
                wmb + ((size_t)(k * COUT + ob + o) * CIN + ic) + c4 * 8;
            uint32_t dst = ws_a + (uint32_t)(st * WS_ST + row * XR) * 2 + c4 * 16;
            cp16(dst, src);
        }
        CP_COMMIT();
    };
    // ---- issue x LDGs for chunk into regs (latency hidden under MMAs) ----
    auto load_x = [&](int ic) {
#pragma unroll
        for (int j = 0; j < 17; ++j) {
            int u = tid + NTH * j;
            if (u < ICH * XT) {
                int i  = u / XT;
                int tl = u - i * XT;
                int t  = tb + tl - 2;
                t = (t < 0) ? -t : ((t >= TLEN) ? (2 * TLEN - 2 - t) : t);
                xr[j] = ldg_f32(xb + (size_t)(ic + i) * TLEN + t);
            }
        }
    };
    // ---- convert + store x regs into stage st ----
    auto store_x = [&](int st) {
#pragma unroll
        for (int j = 0; j < 17; ++j) {
            int u = tid + NTH * j;
            if (u < ICH * XT) {
                int i  = u / XT;
                int tl = u - i * XT;
                xs[st * XS_ST + tl * XR + i] = __float2half_rn(xr[j]);
            }
        }
    };

    // ---- prologue: fill stage 0 ----
    prefetch_w(0, 0);
    load_x(0);
    store_x(0);
    CP_WAIT0();
    __syncthreads();

    for (int c = 0; c < NCH; ++c) {
        const int st = c & 1;
        const int nst = st ^ 1;
        if (c + 1 < NCH) {
            prefetch_w((c + 1) * ICH, nst);
            load_x((c + 1) * ICH);
        }

        // ---- MMA over stage st ----
        const __half* wsp = ws + st * WS_ST;
        const __half* xsp = xs + st * XS_ST;

        for (int tap = 0; tap < KS; ++tap) {
#pragma unroll
            for (int k16 = 0; k16 < ICH; k16 += 16) {
                unsigned ah[2][4];
#pragma unroll
                for (int mt = 0; mt < 2; ++mt) {
                    int row = tap * OTI + wo * 32 + mt * 16 + lq;
                    int col = k16 + lr * 2;
                    const __half* ph = wsp + row * XR + col;
                    ah[mt][0] = lds32(ph);
                    ah[mt][1] = lds32(ph + 8 * XR);
                    ah[mt][2] = lds32(ph + 8);
                    ah[mt][3] = lds32(ph + 8 * XR + 8);
                }
#pragma unroll
                for (int nt = 0; nt < 8; ++nt) {
                    int trow = wt * 64 + nt * 8 + lq + tap;
                    int col  = k16 + lr * 2;
                    const __half* ph = xsp + trow * XR + col;
                    unsigned bh0 = lds32(ph), bh1 = lds32(ph + 8);
#pragma unroll
                    for (int mt = 0; mt < 2; ++mt)
                        mma16816(acc[mt][nt], ah[mt], bh0, bh1);
                }
            }
        }

        if (c + 1 < NCH) {
            store_x(nst);
            CP_WAIT0();
        }
        __syncthreads();
    }

    // ---- epilogue: leaky relu + store ----
#pragma unroll
    for (int mt = 0; mt < 2; ++mt) {
#pragma unroll
        for (int nt = 0; nt < 8; ++nt) {
            int o0 = ob + wo * 32 + mt * 16 + lq;
            int t0 = tb + wt * 64 + nt * 8 + lr * 2;
            float z0 = acc[mt][nt][0], z1 = acc[mt][nt][1];
            float z2 = acc[mt][nt][2], z3 = acc[mt][nt][3];
            z0 = (z0 > 0.f) ? z0 : 0.2f * z0;
            z1 = (z1 > 0.f) ? z1 : 0.2f * z1;
            z2 = (z2 > 0.f) ? z2 : 0.2f * z2;
            z3 = (z3 > 0.f) ? z3 : 0.2f * z3;
            float* p0 = out + ((size_t)b * COUT + o0) * TLEN + t0;
            *(float2*)p0 = make_float2(z0, z1);
            *(float2*)(p0 + 8 * TLEN) = make_float2(z2, z3);
        }
    }
}

// ---------------------------------------------------------------------------
extern "C" void kernel_launch(void* const* d_in, const int* in_sizes, int n_in,
                              void* d_out, int out_size) {
    const float* x       = (const float*)d_in[0];   // [16,256,8192]
    const float* c_trg   = (const float*)d_in[1];   // [16,128]
    const float* style_w = (const float*)d_in[2];   // [256,128]
    const float* style_b = (const float*)d_in[3];   // [256]
    const float* weight  = (const float*)d_in[4];   // [1,256,256,5]
    float* out = (float*)d_out;

    size_t conv_elems = (size_t)NB * COUT * TLEN;   // 33,554,432
    int n_tail = ((size_t)out_size > conv_elems)
               ? (int)((size_t)out_size - conv_elems) : 0;

    style_kernel<<<(NB * CIN) / 8, 256>>>(c_trg, style_w, style_b,
                                          out + conv_elems, n_tail);
    wmfused_kernel<<<NB * COUT, 256>>>(weight);

    static bool attr_done = false;
    if (!attr_done) {
        cudaFuncSetAttribute(conv_kernel,
                             cudaFuncAttributeMaxDynamicSharedMemorySize,
                             SMEM_BYTES);
        attr_done = true;
    }
    dim3 grid(TLEN / TTI, COUT / OTI, NB);        // (32, 2, 16)
    conv_kernel<<<grid, NTH, SMEM_BYTES>>>(x, out);
}